// round 11
// baseline (speedup 1.0000x reference)
#include <cuda_runtime.h>
#include <cuda_bf16.h>
#include <cstdint>

// Holt-Winters additive triple smoothing (gamma unused; season static):
//   out[b,0] = series[b,0] + init_trend
//   sea_t    = init_season[(t - shift_b) mod SLEN]
//   smooth'  = alpha*(y_t - sea_t) + (1-alpha)*(smooth + trend)
//   trend'   = beta*(smooth' - smooth) + (1-beta)*trend
//   out[b,t] = smooth' + trend' + sea_t
//
// R10 = R8 geometry (2 rows/thread ILP on the serial chain, 64-row
// single-warp blocks, 1024 blocks) + R9 season-in-registers (phase-
// templated chunk bodies, zero per-step season LDS/ALU) + prefetch
// depth 2 (3 staging buffers, cp.async.wait_group 1) so each warp's
// DRAM stream never idles during the chain-bound compute phase.

constexpr int ROWS    = 64;   // rows per block
constexpr int THREADS = 32;   // one warp
constexpr int C       = 32;   // time-steps per chunk
constexpr int CH4     = C / 4;        // 8 float4 per row-chunk
constexpr int S       = 36;   // smem row stride (floats)
constexpr int NCH     = 16;   // 512/32
constexpr int NBUF    = 3;    // prefetch depth 2

__device__ __forceinline__ uint32_t smem_u32(const void* p) {
    return (uint32_t)__cvta_generic_to_shared(p);
}
__device__ __forceinline__ void cp_async16(uint32_t dst, const void* src) {
    asm volatile("cp.async.cg.shared.global [%0], [%1], 16;\n"
                 :: "r"(dst), "l"(src) : "memory");
}
__device__ __forceinline__ void cp_commit() {
    asm volatile("cp.async.commit_group;\n" ::: "memory");
}
template <int N>
__device__ __forceinline__ void cp_wait() {
    asm volatile("cp.async.wait_group %0;\n" :: "n"(N) : "memory");
}

__device__ __forceinline__ float hw_step(float y, float sea,
                                         float& smooth, float& trend,
                                         float alpha, float oma,
                                         float beta, float omb)
{
    float sn = alpha * (y - sea) + oma * (smooth + trend);
    float tn = beta * (sn - smooth) + omb * trend;
    smooth = sn;
    trend  = tn;
    return sn + tn + sea;
}

__device__ __forceinline__ void issue_prefetch(
    int ch, int lane, int row0, int T,
    const float* __restrict__ series, float (&s_in)[NBUF][ROWS * S])
{
    const float* src = series + (size_t)ch * C;
    float* bufp = s_in[ch % NBUF];
    #pragma unroll
    for (int k = 0; k < (ROWS * CH4) / THREADS; ++k) {
        int qq = k * THREADS + lane;
        int r  = qq >> 3;
        int f4 = qq & 7;
        cp_async16(smem_u32(&bufp[r * S + f4 * 4]),
                   src + (size_t)(row0 + r) * T + f4 * 4);
    }
}

// One chunk: wait (depth-2), kick prefetch ch+2, run 32 steps for two rows
// with compile-time season phase PH, stage outputs, store coalesced.
template<int PH, bool FIRST>
__device__ __forceinline__ void process_chunk(
    int ch, int lane, int row0,
    const float* __restrict__ series, float4* __restrict__ dstv,
    float (&s_in)[NBUF][ROWS * S], float* __restrict__ s_out,
    float& smoothA, float& trendA, float& smoothB, float& trendB,
    const float (&qA)[12], const float (&qB)[12],
    float alpha, float oma, float beta, float omb, float init_trend,
    int T, int t4)
{
    cp_wait<1>();    // oldest group (chunk ch) retired; ch+1 may still fly
    __syncwarp();    // cross-lane visibility; retires reads of buf being
                     // overwritten by the prefetch below (compute ch-1 done)

    if (ch + 2 < NCH) issue_prefetch(ch + 2, lane, row0, T, series, s_in);
    cp_commit();     // one group per iteration (possibly empty) keeps the
                     // wait<1> accounting aligned

    // compute: two independent rows per thread (2x ILP on the chain)
    {
        const float* base = s_in[ch % NBUF];
        const float4* rinA  = (const float4*)(base + lane * S);
        const float4* rinB  = (const float4*)(base + (lane + 32) * S);
        float4*       routA = (float4*)(s_out + lane * S);
        float4*       routB = (float4*)(s_out + (lane + 32) * S);

        #pragma unroll
        for (int g = 0; g < CH4; ++g) {
            float4 a = rinA[g];
            float4 b = rinB[g];
            float4 oa, ob;
            if (FIRST && g == 0) {
                smoothA = a.x; trendA = init_trend;
                smoothB = b.x; trendB = init_trend;
                oa.x = smoothA + trendA;
                ob.x = smoothB + trendB;
            } else {
                oa.x = hw_step(a.x, qA[(PH + g * 4 + 0) % 12], smoothA, trendA,
                               alpha, oma, beta, omb);
                ob.x = hw_step(b.x, qB[(PH + g * 4 + 0) % 12], smoothB, trendB,
                               alpha, oma, beta, omb);
            }
            oa.y = hw_step(a.y, qA[(PH + g * 4 + 1) % 12], smoothA, trendA,
                           alpha, oma, beta, omb);
            ob.y = hw_step(b.y, qB[(PH + g * 4 + 1) % 12], smoothB, trendB,
                           alpha, oma, beta, omb);
            oa.z = hw_step(a.z, qA[(PH + g * 4 + 2) % 12], smoothA, trendA,
                           alpha, oma, beta, omb);
            ob.z = hw_step(b.z, qB[(PH + g * 4 + 2) % 12], smoothB, trendB,
                           alpha, oma, beta, omb);
            oa.w = hw_step(a.w, qA[(PH + g * 4 + 3) % 12], smoothA, trendA,
                           alpha, oma, beta, omb);
            ob.w = hw_step(b.w, qB[(PH + g * 4 + 3) % 12], smoothB, trendB,
                           alpha, oma, beta, omb);
            routA[g] = oa;
            routB[g] = ob;
        }
    }
    __syncwarp();    // s_out complete across lanes

    // store: quarter-warp = one row's 128B line (coalesced STG.128)
    #pragma unroll
    for (int k = 0; k < (ROWS * CH4) / THREADS; ++k) {
        int qq = k * THREADS + lane;
        int r  = qq >> 3;
        int f4 = qq & 7;
        const float4* p = (const float4*)(s_out + r * S) + f4;
        dstv[(size_t)(row0 + r) * t4 + ch * CH4 + f4] = *p;
    }
    // next chunk's top __syncwarp orders these s_out reads before overwrite
}

__global__ __launch_bounds__(THREADS)
void hw_kernel(const float* __restrict__ series,
               const int*   __restrict__ shifts,
               const float* __restrict__ alpha_p,
               const float* __restrict__ beta_p,
               const float* __restrict__ season_g,
               const float* __restrict__ init_trend_p,
               float* __restrict__ out,
               int B, int T)
{
    __shared__ float s_in [NBUF][ROWS * S];  // 3 x 9216 B
    __shared__ float s_out[ROWS * S];        //     9216 B

    const int lane = threadIdx.x;
    const int row0 = blockIdx.x * ROWS;

    const float alpha      = *alpha_p;
    const float beta       = *beta_p;
    const float init_trend = *init_trend_p;
    const float oma = 1.0f - alpha;
    const float omb = 1.0f - beta;

    // pre-rotated season registers: step t (>=1) of row uses q[t mod 12],
    // where q[j] = season[(j - shift_row) mod 12]
    float qA[12], qB[12];
    {
        int shiftA = shifts[row0 + lane];
        int shiftB = shifts[row0 + lane + 32];
        int mA = (-shiftA) % 12; if (mA < 0) mA += 12;
        int mB = (-shiftB) % 12; if (mB < 0) mB += 12;
        #pragma unroll
        for (int j = 0; j < 12; ++j) {
            qA[j] = season_g[mA];
            qB[j] = season_g[mB];
            mA = (mA + 1 == 12) ? 0 : mA + 1;
            mB = (mB + 1 == 12) ? 0 : mB + 1;
        }
    }

    const int t4 = T >> 2;
    float4* __restrict__ dstv = (float4*)out;

    float smoothA = 0.0f, trendA = 0.0f;
    float smoothB = 0.0f, trendB = 0.0f;

    // prologue: prefetch chunks 0 and 1 (two committed groups in flight)
    issue_prefetch(0, lane, row0, T, series, s_in);
    cp_commit();
    issue_prefetch(1, lane, row0, T, series, s_in);
    cp_commit();

    // chunk 0: phase 0, contains the t=0 special case
    process_chunk<0, true>(0, lane, row0, series, dstv, s_in, s_out,
                           smoothA, trendA, smoothB, trendB, qA, qB,
                           alpha, oma, beta, omb, init_trend, T, t4);

    // chunks 1..15: season phase (32*ch mod 12) cycles 8, 4, 0
    #pragma unroll 1
    for (int c = 1; c < NCH; c += 3) {
        process_chunk<8, false>(c,     lane, row0, series, dstv, s_in, s_out,
                                smoothA, trendA, smoothB, trendB, qA, qB,
                                alpha, oma, beta, omb, init_trend, T, t4);
        process_chunk<4, false>(c + 1, lane, row0, series, dstv, s_in, s_out,
                                smoothA, trendA, smoothB, trendB, qA, qB,
                                alpha, oma, beta, omb, init_trend, T, t4);
        process_chunk<0, false>(c + 2, lane, row0, series, dstv, s_in, s_out,
                                smoothA, trendA, smoothB, trendB, qA, qB,
                                alpha, oma, beta, omb, init_trend, T, t4);
    }
}

// Generic fallback (shape-safe) for any B/T/slen.
__global__ __launch_bounds__(256)
void hw_kernel_generic(const float* __restrict__ series,
                       const int*   __restrict__ shifts,
                       const float* __restrict__ alpha_p,
                       const float* __restrict__ beta_p,
                       const float* __restrict__ season_g,
                       const float* __restrict__ init_trend_p,
                       float* __restrict__ out,
                       int B, int T, int slen)
{
    int row = blockIdx.x * blockDim.x + threadIdx.x;
    if (row >= B) return;
    const float alpha = *alpha_p, beta = *beta_p;
    const float oma = 1.0f - alpha, omb = 1.0f - beta;
    int shift = shifts[row];
    int idx = (1 - shift) % slen; if (idx < 0) idx += slen;
    const float* src = series + (size_t)row * T;
    float* dst = out + (size_t)row * T;
    float smooth = src[0], trend = *init_trend_p;
    dst[0] = smooth + trend;
    for (int t = 1; t < T; ++t) {
        float sea = season_g[idx];
        idx = (idx + 1 == slen) ? 0 : idx + 1;
        dst[t] = hw_step(src[t], sea, smooth, trend, alpha, oma, beta, omb);
    }
}

extern "C" void kernel_launch(void* const* d_in, const int* in_sizes, int n_in,
                              void* d_out, int out_size)
{
    // 0: series f32 [B*T]   1: shifts i32 [B]   2: alpha   3: beta
    // 4: gamma (unused)     5: init_season [SLEN]   6: init_trend   7: n_preds
    const float* series     = (const float*)d_in[0];
    const int*   shifts     = (const int*)  d_in[1];
    const float* alpha_p    = (const float*)d_in[2];
    const float* beta_p     = (const float*)d_in[3];
    const float* season     = (const float*)d_in[5];
    const float* init_trend = (const float*)d_in[6];
    float* out = (float*)d_out;

    int B    = in_sizes[1];
    int T    = in_sizes[0] / B;      // 512
    int slen = in_sizes[5];          // 12

    if (slen == 12 && T == 512 && (B % ROWS) == 0) {
        int blocks = B / ROWS;       // 1024
        hw_kernel<<<blocks, THREADS>>>(series, shifts, alpha_p, beta_p,
                                       season, init_trend, out, B, T);
    } else {
        int threads = 256;
        int blocks  = (B + threads - 1) / threads;
        hw_kernel_generic<<<blocks, threads>>>(series, shifts, alpha_p, beta_p,
                                               season, init_trend, out,
                                               B, T, slen);
    }
}

// round 12
// speedup vs baseline: 1.0646x; 1.0646x over previous
#include <cuda_runtime.h>
#include <cuda_bf16.h>
#include <cstdint>

// Holt-Winters additive triple smoothing (gamma unused; season static):
//   out[b,0] = series[b,0] + init_trend
//   sea_t    = init_season[(t - shift_b) mod SLEN]
//   smooth'  = alpha*(y_t - sea_t) + (1-alpha)*(smooth + trend)
//   trend'   = beta*(smooth' - smooth) + (1-beta)*trend
//   out[b,t] = smooth' + trend' + sea_t
//
// R12 = R8 geometry (64-row single-warp blocks, 2 rows/thread ILP on the
// serial chain, depth-1 double-buffered cp.async, 1024 blocks) + phase-
// templated season access from a TRANSPOSED smem table s_q[j][lane]
// (compile-time j, lane-indexed bank -> conflict-free LDS, zero index ALU,
// zero extra registers). R10 showed season-in-REGISTERS + depth-2 blows
// regs (253) and smem residency; this keeps R8's budget.

constexpr int ROWS    = 64;   // rows per block
constexpr int THREADS = 32;   // one warp
constexpr int C       = 32;   // time-steps per chunk
constexpr int CH4     = C / 4;        // 8 float4 per row-chunk
constexpr int S       = 36;   // smem row stride (floats)
constexpr int NCH     = 16;   // 512/32

__device__ __forceinline__ uint32_t smem_u32(const void* p) {
    return (uint32_t)__cvta_generic_to_shared(p);
}
__device__ __forceinline__ void cp_async16(uint32_t dst, const void* src) {
    asm volatile("cp.async.cg.shared.global [%0], [%1], 16;\n"
                 :: "r"(dst), "l"(src) : "memory");
}
__device__ __forceinline__ void cp_commit() {
    asm volatile("cp.async.commit_group;\n" ::: "memory");
}
template <int N>
__device__ __forceinline__ void cp_wait() {
    asm volatile("cp.async.wait_group %0;\n" :: "n"(N) : "memory");
}

__device__ __forceinline__ float hw_step(float y, float sea,
                                         float& smooth, float& trend,
                                         float alpha, float oma,
                                         float beta, float omb)
{
    float sn = alpha * (y - sea) + oma * (smooth + trend);
    float tn = beta * (sn - smooth) + omb * trend;
    smooth = sn;
    trend  = tn;
    return sn + tn + sea;
}

// One chunk: wait for its staged tile, kick prefetch of ch+1, run 32 steps
// for two rows with compile-time season phase PH, stage outputs, store.
// Season: s_qA/s_qB are [12][32] transposed tables; index j is compile-time
// -> LDS with immediate offset, bank = lane (conflict-free).
template<int PH, bool FIRST>
__device__ __forceinline__ void process_chunk(
    int ch, int lane, int row0,
    const float* __restrict__ series, float4* __restrict__ dstv,
    float (&s_in)[2][ROWS * S], float* __restrict__ s_out,
    const float* __restrict__ s_qA, const float* __restrict__ s_qB,
    float& smoothA, float& trendA, float& smoothB, float& trendB,
    float alpha, float oma, float beta, float omb, float init_trend,
    int T, int t4)
{
    const int buf = ch & 1;

    cp_wait<0>();    // chunk ch's tile landed
    __syncwarp();    // cross-lane visibility; retires prior reads of buf^1

    // prefetch chunk ch+1 into the other buffer (flies during compute/store)
    if (ch + 1 < NCH) {
        const float* src = series + (size_t)(ch + 1) * C;
        #pragma unroll
        for (int k = 0; k < (ROWS * CH4) / THREADS; ++k) {
            int qq = k * THREADS + lane;
            int r  = qq >> 3;
            int f4 = qq & 7;
            cp_async16(smem_u32(&s_in[buf ^ 1][r * S + f4 * 4]),
                       src + (size_t)(row0 + r) * T + f4 * 4);
        }
    }
    cp_commit();

    // compute: two independent rows per thread (2x ILP on the chain)
    {
        const float* base = s_in[buf];
        const float4* rinA  = (const float4*)(base + lane * S);
        const float4* rinB  = (const float4*)(base + (lane + 32) * S);
        float4*       routA = (float4*)(s_out + lane * S);
        float4*       routB = (float4*)(s_out + (lane + 32) * S);

        #pragma unroll
        for (int g = 0; g < CH4; ++g) {
            float4 a = rinA[g];
            float4 b = rinB[g];
            float4 oa, ob;
            // compile-time season row indices for the 4 steps of this group
            constexpr int J0 = 0;  // placeholder; real ones below per lane use
            (void)J0;
            const float sA0 = s_qA[((PH + g * 4 + 0) % 12) * 32 + lane];
            const float sB0 = s_qB[((PH + g * 4 + 0) % 12) * 32 + lane];
            const float sA1 = s_qA[((PH + g * 4 + 1) % 12) * 32 + lane];
            const float sB1 = s_qB[((PH + g * 4 + 1) % 12) * 32 + lane];
            const float sA2 = s_qA[((PH + g * 4 + 2) % 12) * 32 + lane];
            const float sB2 = s_qB[((PH + g * 4 + 2) % 12) * 32 + lane];
            const float sA3 = s_qA[((PH + g * 4 + 3) % 12) * 32 + lane];
            const float sB3 = s_qB[((PH + g * 4 + 3) % 12) * 32 + lane];

            if (FIRST && g == 0) {
                smoothA = a.x; trendA = init_trend;
                smoothB = b.x; trendB = init_trend;
                oa.x = smoothA + trendA;
                ob.x = smoothB + trendB;
            } else {
                oa.x = hw_step(a.x, sA0, smoothA, trendA, alpha, oma, beta, omb);
                ob.x = hw_step(b.x, sB0, smoothB, trendB, alpha, oma, beta, omb);
            }
            oa.y = hw_step(a.y, sA1, smoothA, trendA, alpha, oma, beta, omb);
            ob.y = hw_step(b.y, sB1, smoothB, trendB, alpha, oma, beta, omb);
            oa.z = hw_step(a.z, sA2, smoothA, trendA, alpha, oma, beta, omb);
            ob.z = hw_step(b.z, sB2, smoothB, trendB, alpha, oma, beta, omb);
            oa.w = hw_step(a.w, sA3, smoothA, trendA, alpha, oma, beta, omb);
            ob.w = hw_step(b.w, sB3, smoothB, trendB, alpha, oma, beta, omb);
            routA[g] = oa;
            routB[g] = ob;
        }
    }
    __syncwarp();    // s_out complete across lanes

    // store: quarter-warp = one row's 128B line (coalesced STG.128)
    #pragma unroll
    for (int k = 0; k < (ROWS * CH4) / THREADS; ++k) {
        int qq = k * THREADS + lane;
        int r  = qq >> 3;
        int f4 = qq & 7;
        const float4* p = (const float4*)(s_out + r * S) + f4;
        dstv[(size_t)(row0 + r) * t4 + ch * CH4 + f4] = *p;
    }
    // next chunk's top __syncwarp orders these s_out reads before overwrite
}

__global__ __launch_bounds__(THREADS)
void hw_kernel(const float* __restrict__ series,
               const int*   __restrict__ shifts,
               const float* __restrict__ alpha_p,
               const float* __restrict__ beta_p,
               const float* __restrict__ season_g,
               const float* __restrict__ init_trend_p,
               float* __restrict__ out,
               int B, int T)
{
    __shared__ float s_in [2][ROWS * S];  // 2 x 9216 B
    __shared__ float s_out[ROWS * S];     //     9216 B
    __shared__ float s_qA[12 * 32];       // 1536 B  (season, rotated, transposed)
    __shared__ float s_qB[12 * 32];       // 1536 B

    const int lane = threadIdx.x;
    const int row0 = blockIdx.x * ROWS;

    const float alpha      = *alpha_p;
    const float beta       = *beta_p;
    const float init_trend = *init_trend_p;
    const float oma = 1.0f - alpha;
    const float omb = 1.0f - beta;

    // season tables: step t (>=1) of row uses q[t mod 12],
    //   q[j] = season[(j - shift_row) mod 12]; stored transposed [j][lane].
    {
        int shiftA = shifts[row0 + lane];
        int shiftB = shifts[row0 + lane + 32];
        int mA = (-shiftA) % 12; if (mA < 0) mA += 12;
        int mB = (-shiftB) % 12; if (mB < 0) mB += 12;
        #pragma unroll
        for (int j = 0; j < 12; ++j) {
            s_qA[j * 32 + lane] = season_g[mA];
            s_qB[j * 32 + lane] = season_g[mB];
            mA = (mA + 1 == 12) ? 0 : mA + 1;
            mB = (mB + 1 == 12) ? 0 : mB + 1;
        }
    }

    const int t4 = T >> 2;
    float4* __restrict__ dstv = (float4*)out;

    float smoothA = 0.0f, trendA = 0.0f;
    float smoothB = 0.0f, trendB = 0.0f;

    // prologue: prefetch chunk 0 into buf 0 (coalesced 128B lines)
    #pragma unroll
    for (int k = 0; k < (ROWS * CH4) / THREADS; ++k) {
        int qq = k * THREADS + lane;
        int r  = qq >> 3;
        int f4 = qq & 7;
        cp_async16(smem_u32(&s_in[0][r * S + f4 * 4]),
                   series + (size_t)(row0 + r) * T + f4 * 4);
    }
    cp_commit();
    __syncwarp();    // season tables visible before compute

    // chunk 0: phase 0, contains the t=0 special case
    process_chunk<0, true>(0, lane, row0, series, dstv, s_in, s_out,
                           s_qA, s_qB, smoothA, trendA, smoothB, trendB,
                           alpha, oma, beta, omb, init_trend, T, t4);

    // chunks 1..15: season phase (32*ch mod 12) cycles 8, 4, 0
    #pragma unroll 1
    for (int c = 1; c < NCH; c += 3) {
        process_chunk<8, false>(c,     lane, row0, series, dstv, s_in, s_out,
                                s_qA, s_qB, smoothA, trendA, smoothB, trendB,
                                alpha, oma, beta, omb, init_trend, T, t4);
        process_chunk<4, false>(c + 1, lane, row0, series, dstv, s_in, s_out,
                                s_qA, s_qB, smoothA, trendA, smoothB, trendB,
                                alpha, oma, beta, omb, init_trend, T, t4);
        process_chunk<0, false>(c + 2, lane, row0, series, dstv, s_in, s_out,
                                s_qA, s_qB, smoothA, trendA, smoothB, trendB,
                                alpha, oma, beta, omb, init_trend, T, t4);
    }
}

// Generic fallback (shape-safe) for any B/T/slen.
__global__ __launch_bounds__(256)
void hw_kernel_generic(const float* __restrict__ series,
                       const int*   __restrict__ shifts,
                       const float* __restrict__ alpha_p,
                       const float* __restrict__ beta_p,
                       const float* __restrict__ season_g,
                       const float* __restrict__ init_trend_p,
                       float* __restrict__ out,
                       int B, int T, int slen)
{
    int row = blockIdx.x * blockDim.x + threadIdx.x;
    if (row >= B) return;
    const float alpha = *alpha_p, beta = *beta_p;
    const float oma = 1.0f - alpha, omb = 1.0f - beta;
    int shift = shifts[row];
    int idx = (1 - shift) % slen; if (idx < 0) idx += slen;
    const float* src = series + (size_t)row * T;
    float* dst = out + (size_t)row * T;
    float smooth = src[0], trend = *init_trend_p;
    dst[0] = smooth + trend;
    for (int t = 1; t < T; ++t) {
        float sea = season_g[idx];
        idx = (idx + 1 == slen) ? 0 : idx + 1;
        dst[t] = hw_step(src[t], sea, smooth, trend, alpha, oma, beta, omb);
    }
}

extern "C" void kernel_launch(void* const* d_in, const int* in_sizes, int n_in,
                              void* d_out, int out_size)
{
    // 0: series f32 [B*T]   1: shifts i32 [B]   2: alpha   3: beta
    // 4: gamma (unused)     5: init_season [SLEN]   6: init_trend   7: n_preds
    const float* series     = (const float*)d_in[0];
    const int*   shifts     = (const int*)  d_in[1];
    const float* alpha_p    = (const float*)d_in[2];
    const float* beta_p     = (const float*)d_in[3];
    const float* season     = (const float*)d_in[5];
    const float* init_trend = (const float*)d_in[6];
    float* out = (float*)d_out;

    int B    = in_sizes[1];
    int T    = in_sizes[0] / B;      // 512
    int slen = in_sizes[5];          // 12

    if (slen == 12 && T == 512 && (B % ROWS) == 0) {
        int blocks = B / ROWS;       // 1024
        hw_kernel<<<blocks, THREADS>>>(series, shifts, alpha_p, beta_p,
                                       season, init_trend, out, B, T);
    } else {
        int threads = 256;
        int blocks  = (B + threads - 1) / threads;
        hw_kernel_generic<<<blocks, threads>>>(series, shifts, alpha_p, beta_p,
                                               season, init_trend, out,
                                               B, T, slen);
    }
}

// round 13
// speedup vs baseline: 1.1969x; 1.1242x over previous
#include <cuda_runtime.h>
#include <cuda_bf16.h>
#include <cstdint>

// Holt-Winters additive triple smoothing (gamma unused; season static).
// Reference per-step math (t>=1):
//   sn  = alpha*(y - sea) + (1-alpha)*(smooth + trend)
//   tn  = beta*(sn - smooth) + (1-beta)*trend
//   out = sn + tn + sea
// R13 reformulation (exact-arithmetic equivalent, carry f = smooth+trend):
//   e  = y - (sea + f)
//   tn = trend + (alpha*beta)*e        // == beta*(sn-smooth)+(1-beta)*trend
//   fn = (f + alpha*e) + tn            // == sn + tn == next f
//   out= fn + sea
// 6 FP ops/step vs 9, and f' = fn directly.
//
// Geometry = R8 (the proven best): 64-row single-warp blocks, 2 rows/thread
// ILP on the serial chain, depth-1 double-buffered cp.async staging, 1024
// blocks. Season: per-row rotation baked into a packed float2 table
// s_q2[t mod 12][lane] = (qA, qB) -> one conflict-free LDS.64 + one SHARED
// index roll per 2-row step (replaces two conflicted gathers + two index
// chains). Single code body - no template duplication (R9/R10/R12 showed
// 4x body instantiation thrashes I$ and regresses).

constexpr int ROWS    = 64;   // rows per block
constexpr int THREADS = 32;   // one warp
constexpr int C       = 32;   // time-steps per chunk
constexpr int CH4     = C / 4;        // 8 float4 per row-chunk
constexpr int S       = 36;   // smem row stride (floats)
constexpr int NCH     = 16;   // 512/32

__device__ __forceinline__ uint32_t smem_u32(const void* p) {
    return (uint32_t)__cvta_generic_to_shared(p);
}
__device__ __forceinline__ void cp_async16(uint32_t dst, const void* src) {
    asm volatile("cp.async.cg.shared.global [%0], [%1], 16;\n"
                 :: "r"(dst), "l"(src) : "memory");
}
__device__ __forceinline__ void cp_commit() {
    asm volatile("cp.async.commit_group;\n" ::: "memory");
}
template <int N>
__device__ __forceinline__ void cp_wait() {
    asm volatile("cp.async.wait_group %0;\n" :: "n"(N) : "memory");
}

// 6-op step on the (f, trend) carry.
__device__ __forceinline__ float hw_step_f(float y, float sea,
                                           float& f, float& tr,
                                           float al, float ab)
{
    float e  = y - (sea + f);
    float tn = fmaf(ab, e, tr);
    float fn = fmaf(al, e, f) + tn;
    tr = tn;
    f  = fn;
    return fn + sea;
}

__global__ __launch_bounds__(THREADS)
void hw_kernel(const float* __restrict__ series,
               const int*   __restrict__ shifts,
               const float* __restrict__ alpha_p,
               const float* __restrict__ beta_p,
               const float* __restrict__ season_g,
               const float* __restrict__ init_trend_p,
               float* __restrict__ out,
               int B, int T)
{
    __shared__ float  s_in [2][ROWS * S];  // 2 x 9216 B
    __shared__ float  s_out[ROWS * S];     //     9216 B
    __shared__ float2 s_q2 [12 * 32];      // 3072 B: [j][lane] = (qA, qB)

    const int lane = threadIdx.x;
    const int row0 = blockIdx.x * ROWS;

    const float alpha      = *alpha_p;
    const float beta       = *beta_p;
    const float init_trend = *init_trend_p;
    const float ab = alpha * beta;

    // Build packed season table: step t (>=1) of any row uses j = t mod 12;
    //   qX[j] = season[(j - shift_rowX) mod 12]  (rotation baked per row)
    {
        int shiftA = shifts[row0 + lane];
        int shiftB = shifts[row0 + lane + 32];
        int mA = (-shiftA) % 12; if (mA < 0) mA += 12;
        int mB = (-shiftB) % 12; if (mB < 0) mB += 12;
        #pragma unroll
        for (int j = 0; j < 12; ++j) {
            s_q2[j * 32 + lane] = make_float2(season_g[mA], season_g[mB]);
            mA = (mA + 1 == 12) ? 0 : mA + 1;
            mB = (mB + 1 == 12) ? 0 : mB + 1;
        }
    }

    const int t4 = T >> 2;
    float4* __restrict__ dstv = (float4*)out;

    float fA = 0.0f, trA = 0.0f;   // f = smooth + trend carry
    float fB = 0.0f, trB = 0.0f;
    int   j  = 1;                  // season index (t mod 12), shared by rows

    // prologue: prefetch chunk 0 into buf 0 (coalesced 128B lines)
    #pragma unroll
    for (int k = 0; k < (ROWS * CH4) / THREADS; ++k) {
        int qq = k * THREADS + lane;
        int r  = qq >> 3;
        int f4 = qq & 7;
        cp_async16(smem_u32(&s_in[0][r * S + f4 * 4]),
                   series + (size_t)(row0 + r) * T + f4 * 4);
    }
    cp_commit();
    __syncwarp();    // season table visible before first compute

    #pragma unroll 1
    for (int ch = 0; ch < NCH; ++ch) {
        const int buf = ch & 1;

        cp_wait<0>();    // chunk ch's tile landed
        __syncwarp();    // cross-lane visibility; retires reads of buf^1

        // prefetch chunk ch+1 (flies during compute + store)
        if (ch + 1 < NCH) {
            const float* src = series + (size_t)(ch + 1) * C;
            #pragma unroll
            for (int k = 0; k < (ROWS * CH4) / THREADS; ++k) {
                int qq = k * THREADS + lane;
                int r  = qq >> 3;
                int f4 = qq & 7;
                cp_async16(smem_u32(&s_in[buf ^ 1][r * S + f4 * 4]),
                           src + (size_t)(row0 + r) * T + f4 * 4);
            }
        }
        cp_commit();

        // compute: two independent rows per thread (2x ILP on the chain)
        {
            const float* base = s_in[buf];
            const float4* rinA  = (const float4*)(base + lane * S);
            const float4* rinB  = (const float4*)(base + (lane + 32) * S);
            float4*       routA = (float4*)(s_out + lane * S);
            float4*       routB = (float4*)(s_out + (lane + 32) * S);

            #pragma unroll
            for (int g = 0; g < CH4; ++g) {
                float4 a = rinA[g];
                float4 b = rinB[g];
                float4 oa, ob;
                float2 s2;

                if (ch == 0 && g == 0) {
                    // t = 0: out = y0 + init_trend; carry f = y0 + trend
                    trA = init_trend; fA = a.x + init_trend;
                    trB = init_trend; fB = b.x + init_trend;
                    oa.x = fA;
                    ob.x = fB;
                } else {
                    s2 = s_q2[j * 32 + lane];
                    j  = (j + 1 == 12) ? 0 : j + 1;
                    oa.x = hw_step_f(a.x, s2.x, fA, trA, alpha, ab);
                    ob.x = hw_step_f(b.x, s2.y, fB, trB, alpha, ab);
                }
                s2 = s_q2[j * 32 + lane];
                j  = (j + 1 == 12) ? 0 : j + 1;
                oa.y = hw_step_f(a.y, s2.x, fA, trA, alpha, ab);
                ob.y = hw_step_f(b.y, s2.y, fB, trB, alpha, ab);

                s2 = s_q2[j * 32 + lane];
                j  = (j + 1 == 12) ? 0 : j + 1;
                oa.z = hw_step_f(a.z, s2.x, fA, trA, alpha, ab);
                ob.z = hw_step_f(b.z, s2.y, fB, trB, alpha, ab);

                s2 = s_q2[j * 32 + lane];
                j  = (j + 1 == 12) ? 0 : j + 1;
                oa.w = hw_step_f(a.w, s2.x, fA, trA, alpha, ab);
                ob.w = hw_step_f(b.w, s2.y, fB, trB, alpha, ab);

                routA[g] = oa;
                routB[g] = ob;
            }
        }
        __syncwarp();    // s_out complete across lanes

        // store: quarter-warp = one row's 128B line (coalesced STG.128)
        #pragma unroll
        for (int k = 0; k < (ROWS * CH4) / THREADS; ++k) {
            int qq = k * THREADS + lane;
            int r  = qq >> 3;
            int f4 = qq & 7;
            const float4* p = (const float4*)(s_out + r * S) + f4;
            dstv[(size_t)(row0 + r) * t4 + ch * CH4 + f4] = *p;
        }
        // next iteration's top __syncwarp orders these s_out reads before
        // the next compute overwrites s_out.
    }
}

// Generic fallback (shape-safe) for any B/T/slen — original formulation.
__global__ __launch_bounds__(256)
void hw_kernel_generic(const float* __restrict__ series,
                       const int*   __restrict__ shifts,
                       const float* __restrict__ alpha_p,
                       const float* __restrict__ beta_p,
                       const float* __restrict__ season_g,
                       const float* __restrict__ init_trend_p,
                       float* __restrict__ out,
                       int B, int T, int slen)
{
    int row = blockIdx.x * blockDim.x + threadIdx.x;
    if (row >= B) return;
    const float alpha = *alpha_p, beta = *beta_p;
    const float oma = 1.0f - alpha, omb = 1.0f - beta;
    int shift = shifts[row];
    int idx = (1 - shift) % slen; if (idx < 0) idx += slen;
    const float* src = series + (size_t)row * T;
    float* dst = out + (size_t)row * T;
    float smooth = src[0], trend = *init_trend_p;
    dst[0] = smooth + trend;
    for (int t = 1; t < T; ++t) {
        float sea = season_g[idx];
        idx = (idx + 1 == slen) ? 0 : idx + 1;
        float sn = alpha * (src[t] - sea) + oma * (smooth + trend);
        float tn = beta * (sn - smooth) + omb * trend;
        dst[t] = sn + tn + sea;
        smooth = sn; trend = tn;
    }
}

extern "C" void kernel_launch(void* const* d_in, const int* in_sizes, int n_in,
                              void* d_out, int out_size)
{
    // 0: series f32 [B*T]   1: shifts i32 [B]   2: alpha   3: beta
    // 4: gamma (unused)     5: init_season [SLEN]   6: init_trend   7: n_preds
    const float* series     = (const float*)d_in[0];
    const int*   shifts     = (const int*)  d_in[1];
    const float* alpha_p    = (const float*)d_in[2];
    const float* beta_p     = (const float*)d_in[3];
    const float* season     = (const float*)d_in[5];
    const float* init_trend = (const float*)d_in[6];
    float* out = (float*)d_out;

    int B    = in_sizes[1];
    int T    = in_sizes[0] / B;      // 512
    int slen = in_sizes[5];          // 12

    if (slen == 12 && T == 512 && (B % ROWS) == 0) {
        int blocks = B / ROWS;       // 1024
        hw_kernel<<<blocks, THREADS>>>(series, shifts, alpha_p, beta_p,
                                       season, init_trend, out, B, T);
    } else {
        int threads = 256;
        int blocks  = (B + threads - 1) / threads;
        hw_kernel_generic<<<blocks, threads>>>(series, shifts, alpha_p, beta_p,
                                               season, init_trend, out,
                                               B, T, slen);
    }
}